// round 15
// baseline (speedup 1.0000x reference)
#include <cuda_runtime.h>
#include <cuda_fp16.h>
#include <mma.h>

using namespace nvcuda;

#define TT 4096
#define DD 2048
#define FF 4096
#define EE 8
#define XX 2
#define AA (TT * XX)
#define WE ((size_t)DD * FF)          // one expert's weight elems (8M)

#define BM 128
#define BN 64
#define BK 16
#define ALD 24                        // A smem ldm (halves), 48B rows
#define BLD 72                        // B smem ldm (halves) for BN=64
#define DN 128                        // down-GEMM BN
#define DBLD 136                      // down-GEMM B smem ldm (halves), 272B rows
#define NSTG 4                        // cp.async stages
#define SLD 20                        // scratch ldm (floats)
#define MAX_TILES (AA / BM + EE)      // 72
#define ETILES (AA / BM)              // max m-tiles for one expert (64)

// ---------------- scratch (device globals; 192MB total — well inside proven 288MB envelope) ----------------
__device__ __align__(128) __half g_wab[2 * WE];             // 32MB: phase1 = gate|up of expert e; phase2 = Wd of e
__device__ __align__(128) __half g_x16[(size_t)AA * DD];    // sorted x, fp16 (32MB)
__device__ __align__(128) __half g_h16[(size_t)AA * FF];    // silu(g)*u, fp16 (64MB)
__device__ __align__(128) float g_down[(size_t)AA * DD];    // down output, fp32 (64MB)
__device__ int g_tile_e[MAX_TILES];
__device__ int g_tile_row0[MAX_TILES];
__device__ int g_tile_cnt[MAX_TILES];
__device__ int g_tile_estart[EE + 1];
__device__ int g_num_tiles;
__device__ int g_tok[AA];
__device__ int g_pos[AA];

// ---------------- helpers ----------------
__device__ __forceinline__ unsigned smem_u32(const void* p) {
    unsigned a;
    asm("{ .reg .u64 t; cvta.to.shared.u64 t, %1; cvt.u32.u64 %0, t; }" : "=r"(a) : "l"(p));
    return a;
}
__device__ __forceinline__ void cp16(unsigned dst, const void* src) {
    asm volatile("cp.async.ca.shared.global [%0], [%1], 16;" :: "r"(dst), "l"(src) : "memory");
}
__device__ __forceinline__ void cp_commit() { asm volatile("cp.async.commit_group;" ::: "memory"); }
__device__ __forceinline__ void cp_wait2() { asm volatile("cp.async.wait_group 2;" ::: "memory"); }

__device__ __forceinline__ uint4 pack8(const float4 v0, const float4 v1) {
    __half h[8] = {__float2half_rn(v0.x), __float2half_rn(v0.y),
                   __float2half_rn(v0.z), __float2half_rn(v0.w),
                   __float2half_rn(v1.x), __float2half_rn(v1.y),
                   __float2half_rn(v1.z), __float2half_rn(v1.w)};
    return *(const uint4*)h;
}

// ---------------- setup: counting sort + tile table + per-expert tile ranges ----------------
__global__ void setup_kernel(const int* __restrict__ sel) {
    __shared__ int cnt[EE];
    __shared__ int cur[EE];
    const int tid = threadIdx.x;
    if (tid < EE) cnt[tid] = 0;
    __syncthreads();
    for (int a = tid; a < AA; a += blockDim.x) atomicAdd(&cnt[sel[a]], 1);
    __syncthreads();
    if (tid == 0) {
        int o = 0, nt = 0;
        for (int e = 0; e < EE; e++) {
            g_tile_estart[e] = nt;
            cur[e] = o;
            const int c = cnt[e];
            for (int m = 0; m < c; m += BM) {
                g_tile_e[nt] = e;
                g_tile_row0[nt] = o + m;
                g_tile_cnt[nt] = (c - m < BM) ? (c - m) : BM;
                nt++;
            }
            o += c;
        }
        g_tile_estart[EE] = nt;
        g_num_tiles = nt;
    }
    __syncthreads();
    for (int a = tid; a < AA; a += blockDim.x) {
        const int e = sel[a];
        const int p = atomicAdd(&cur[e], 1);
        g_pos[a] = p;
        g_tok[p] = a >> 1;
    }
}

// ---------------- convert x: gather sorted rows -> fp16 ----------------
__global__ void convert_x(const float* __restrict__ x) {
    const int p = blockIdx.x;
    const float4* src = (const float4*)(x + (size_t)g_tok[p] * DD);
    uint4* dst = (uint4*)(g_x16 + (size_t)p * DD);
    for (int i = threadIdx.x; i < DD / 8; i += 256)
        dst[i] = pack8(src[2 * i], src[2 * i + 1]);
}

// ---------------- convert one expert's gate+up weights -> g_wab ----------------
__global__ void convert_gu(const float* __restrict__ Wg, const float* __restrict__ Wu, int e) {
    const size_t i = (size_t)blockIdx.x * blockDim.x + threadIdx.x;   // over 2*WE/8
    const size_t half = WE / 8;
    const float4* src;
    uint4* dst;
    if (i < half) {
        src = (const float4*)(Wg + (size_t)e * WE) + 2 * i;
        dst = (uint4*)g_wab + i;
    } else {
        const size_t j = i - half;
        src = (const float4*)(Wu + (size_t)e * WE) + 2 * j;
        dst = (uint4*)(g_wab + WE) + j;
    }
    *dst = pack8(src[0], src[1]);
}

// ---------------- convert one expert's down weights -> g_wab ----------------
__global__ void convert_wd(const float* __restrict__ Wd, int e) {
    const size_t i = (size_t)blockIdx.x * blockDim.x + threadIdx.x;   // over WE/8
    const float4* src = (const float4*)(Wd + (size_t)e * WE) + 2 * i;
    ((uint4*)g_wab)[i] = pack8(src[0], src[1]);
}

// ================= fused gate+up GEMM (wmma fp16, 4-stage cp.async, fp16 weights, per-expert) =================
__global__ __launch_bounds__(256) void gemm_gateup(int e) {
    __shared__ __align__(16) __half As[NSTG][BM * ALD];      // 4 x 6KB
    __shared__ __align__(16) __half Bgs[NSTG][BK * BLD];     // 4 x 2.25KB
    __shared__ __align__(16) __half Bus[NSTG][BK * BLD];     // 4 x 2.25KB

    const int mt = g_tile_estart[e] + blockIdx.x;
    if (mt >= g_tile_estart[e + 1]) return;
    const int row0 = g_tile_row0[mt];
    const int cnt = g_tile_cnt[mt];
    const int n0 = blockIdx.y * BN;
    const int tid = threadIdx.x;
    const int wid = tid >> 5;
    const int lane = tid & 31;
    const int wm0 = (wid & 3) * 32;
    const int wn0 = (wid >> 2) * 32;

    // A loader: 128 rows x 2 x 16B
    const int lr = tid >> 1, lc = (tid & 1) * 8;
    const int rowc = (lr < cnt) ? lr : 0;
    const __half* pa = g_x16 + (size_t)(row0 + rowc) * DD + lc;
    const unsigned aS[NSTG] = {smem_u32(&As[0][lr * ALD + lc]), smem_u32(&As[1][lr * ALD + lc]),
                               smem_u32(&As[2][lr * ALD + lc]), smem_u32(&As[3][lr * ALD + lc])};
    // B loader: threads 0-127 -> gate (g_wab), 128-255 -> up (g_wab+WE). 16 k-rows x 8 x 16B each.
    const int t2 = tid & 127;
    const int bk = t2 >> 3, bn = (t2 & 7) * 8;
    const __half* wsrc = (tid < 128) ? g_wab : (g_wab + WE);
    const __half* pb = wsrc + (size_t)bk * FF + n0 + bn;
    const unsigned bS[NSTG] = {
        smem_u32((tid < 128 ? &Bgs[0][bk * BLD + bn] : &Bus[0][bk * BLD + bn])),
        smem_u32((tid < 128 ? &Bgs[1][bk * BLD + bn] : &Bus[1][bk * BLD + bn])),
        smem_u32((tid < 128 ? &Bgs[2][bk * BLD + bn] : &Bus[2][bk * BLD + bn])),
        smem_u32((tid < 128 ? &Bgs[3][bk * BLD + bn] : &Bus[3][bk * BLD + bn]))};

    wmma::fragment<wmma::accumulator, 16, 16, 16, float> accg[2][2], accu[2][2];
#pragma unroll
    for (int mi = 0; mi < 2; mi++)
#pragma unroll
        for (int nj = 0; nj < 2; nj++) {
            wmma::fill_fragment(accg[mi][nj], 0.0f);
            wmma::fill_fragment(accu[mi][nj], 0.0f);
        }

    const int NC = DD / BK;  // 128

    auto issue = [&](int c) {
        if (c < NC) {
            const int s = c & 3;
            cp16(aS[s], pa + (size_t)c * BK);
            cp16(bS[s], pb + (size_t)c * BK * FF);
        }
        cp_commit();
    };
    auto compute = [&](int buf) {
        wmma::fragment<wmma::matrix_a, 16, 16, 16, __half, wmma::row_major> aF[2];
        wmma::fragment<wmma::matrix_b, 16, 16, 16, __half, wmma::row_major> bg[2], bu[2];
#pragma unroll
        for (int mi = 0; mi < 2; mi++)
            wmma::load_matrix_sync(aF[mi], &As[buf][(wm0 + mi * 16) * ALD], ALD);
#pragma unroll
        for (int nj = 0; nj < 2; nj++) {
            wmma::load_matrix_sync(bg[nj], &Bgs[buf][wn0 + nj * 16], BLD);
            wmma::load_matrix_sync(bu[nj], &Bus[buf][wn0 + nj * 16], BLD);
        }
#pragma unroll
        for (int mi = 0; mi < 2; mi++)
#pragma unroll
            for (int nj = 0; nj < 2; nj++) {
                wmma::mma_sync(accg[mi][nj], aF[mi], bg[nj], accg[mi][nj]);
                wmma::mma_sync(accu[mi][nj], aF[mi], bu[nj], accu[mi][nj]);
            }
    };

    issue(0);
    issue(1);
    issue(2);

    for (int c = 0; c < NC; c++) {
        cp_wait2();
        __syncthreads();
        issue(c + 3);
        compute(c & 3);
    }

    // epilogue: h16 = silu(g) * u, via per-warp scratch overlaid on A smem
    float* myscr = (float*)&As[0][0] + wid * (16 * SLD);
    const int er = lane >> 1, ec = (lane & 1) * 8;
    __syncthreads();
#pragma unroll
    for (int mi = 0; mi < 2; mi++)
#pragma unroll
        for (int nj = 0; nj < 2; nj++) {
            float gv[8], uv[8];
            wmma::store_matrix_sync(myscr, accg[mi][nj], SLD, wmma::mem_row_major);
            __syncwarp();
#pragma unroll
            for (int q = 0; q < 8; q++) gv[q] = myscr[er * SLD + ec + q];
            __syncwarp();
            wmma::store_matrix_sync(myscr, accu[mi][nj], SLD, wmma::mem_row_major);
            __syncwarp();
#pragma unroll
            for (int q = 0; q < 8; q++) uv[q] = myscr[er * SLD + ec + q];
            __syncwarp();
            const int rin = wm0 + mi * 16 + er;
            if (rin < cnt) {
                __half o[8];
#pragma unroll
                for (int q = 0; q < 8; q++)
                    o[q] = __float2half_rn((gv[q] / (1.0f + __expf(-gv[q]))) * uv[q]);
                *(uint4*)(g_h16 + (size_t)(row0 + rin) * FF + n0 + wn0 + nj * 16 + ec) =
                    *(const uint4*)o;
            }
        }
}

// ================= down GEMM (wmma fp16, 4-stage cp.async, per-expert) — proven R12 core =================
__global__ __launch_bounds__(256) void gemm_down(int e) {
    __shared__ __align__(16) __half As[NSTG][BM * ALD];     // 4 x 6KB
    __shared__ __align__(16) __half Bsm[NSTG][BK * DBLD];   // 4 x 4.25KB

    const int mt = g_tile_estart[e] + blockIdx.x;
    if (mt >= g_tile_estart[e + 1]) return;
    const int row0 = g_tile_row0[mt];
    const int cnt = g_tile_cnt[mt];
    const int n0 = blockIdx.y * DN;
    const int tid = threadIdx.x;
    const int wid = tid >> 5;
    const int lane = tid & 31;
    const int wm0 = (wid & 3) * 32;
    const int wn0 = (wid >> 2) * 64;

    const int lr = tid >> 1, lc = (tid & 1) * 8;
    const int rowc = (lr < cnt) ? lr : 0;
    const __half* pa = g_h16 + (size_t)(row0 + rowc) * FF + lc;
    const unsigned aS[NSTG] = {smem_u32(&As[0][lr * ALD + lc]), smem_u32(&As[1][lr * ALD + lc]),
                               smem_u32(&As[2][lr * ALD + lc]), smem_u32(&As[3][lr * ALD + lc])};
    const int bk = tid >> 4, bn = (tid & 15) * 8;
    const __half* pb = g_wab + (size_t)bk * DD + n0 + bn;   // phase-2 contents = Wd[e] fp16
    const unsigned bS[NSTG] = {smem_u32(&Bsm[0][bk * DBLD + bn]), smem_u32(&Bsm[1][bk * DBLD + bn]),
                               smem_u32(&Bsm[2][bk * DBLD + bn]), smem_u32(&Bsm[3][bk * DBLD + bn])};

    wmma::fragment<wmma::accumulator, 16, 16, 16, float> acc[2][4];
#pragma unroll
    for (int mi = 0; mi < 2; mi++)
#pragma unroll
        for (int nj = 0; nj < 4; nj++) wmma::fill_fragment(acc[mi][nj], 0.0f);

    const int NC = FF / BK;  // 256

    auto issue = [&](int c) {
        if (c < NC) {
            const int s = c & 3;
            cp16(aS[s], pa + (size_t)c * BK);
            cp16(bS[s], pb + (size_t)c * BK * DD);
        }
        cp_commit();
    };
    auto compute = [&](int buf) {
        wmma::fragment<wmma::matrix_a, 16, 16, 16, __half, wmma::row_major> aF[2];
        wmma::fragment<wmma::matrix_b, 16, 16, 16, __half, wmma::row_major> bd[4];
#pragma unroll
        for (int mi = 0; mi < 2; mi++)
            wmma::load_matrix_sync(aF[mi], &As[buf][(wm0 + mi * 16) * ALD], ALD);
#pragma unroll
        for (int nj = 0; nj < 4; nj++)
            wmma::load_matrix_sync(bd[nj], &Bsm[buf][wn0 + nj * 16], DBLD);
#pragma unroll
        for (int mi = 0; mi < 2; mi++)
#pragma unroll
            for (int nj = 0; nj < 4; nj++)
                wmma::mma_sync(acc[mi][nj], aF[mi], bd[nj], acc[mi][nj]);
    };

    issue(0);
    issue(1);
    issue(2);

    for (int c = 0; c < NC; c++) {
        cp_wait2();
        __syncthreads();
        issue(c + 3);
        compute(c & 3);
    }

    float* myscr = (float*)&As[0][0] + wid * (16 * SLD);
    const int er = lane >> 1, ec = (lane & 1) * 8;
    __syncthreads();
#pragma unroll
    for (int mi = 0; mi < 2; mi++)
#pragma unroll
        for (int nj = 0; nj < 4; nj++) {
            wmma::store_matrix_sync(myscr, acc[mi][nj], SLD, wmma::mem_row_major);
            __syncwarp();
            float o[8];
#pragma unroll
            for (int q = 0; q < 8; q++) o[q] = myscr[er * SLD + ec + q];
            __syncwarp();
            const int rin = wm0 + mi * 16 + er;
            if (rin < cnt) {
                float* dst = g_down + (size_t)(row0 + rin) * DD + n0 + wn0 + nj * 16 + ec;
                *(float4*)dst = make_float4(o[0], o[1], o[2], o[3]);
                *(float4*)(dst + 4) = make_float4(o[4], o[5], o[6], o[7]);
            }
        }
}

// ---------------- combine (proven) ----------------
__global__ void combine_kernel(const float* __restrict__ rw, float* __restrict__ out) {
    const int i = blockIdx.x * blockDim.x + threadIdx.x;
    if (i >= TT * (DD / 4)) return;
    const int t = i / (DD / 4);
    const int c = (i % (DD / 4)) * 4;
    const int p0 = g_pos[t * 2 + 0];
    const int p1 = g_pos[t * 2 + 1];
    const float w0 = rw[t * 2 + 0];
    const float w1 = rw[t * 2 + 1];
    const float4 a = *(const float4*)&g_down[(size_t)p0 * DD + c];
    const float4 b = *(const float4*)&g_down[(size_t)p1 * DD + c];
    float4 o;
    o.x = w0 * a.x + w1 * b.x;
    o.y = w0 * a.y + w1 * b.y;
    o.z = w0 * a.z + w1 * b.z;
    o.w = w0 * a.w + w1 * b.w;
    *(float4*)&out[(size_t)t * DD + c] = o;
}

extern "C" void kernel_launch(void* const* d_in, const int* in_sizes, int n_in,
                              void* d_out, int out_size) {
    const float* x   = (const float*)d_in[0];
    const float* rw  = (const float*)d_in[1];
    const int*   sel = (const int*)d_in[2];
    const float* Wg  = (const float*)d_in[3];
    const float* Wu  = (const float*)d_in[4];
    const float* Wd  = (const float*)d_in[5];
    float* out = (float*)d_out;

    const int gu_blk = (int)((2 * WE / 8) / 256);   // 8192
    const int wd_blk = (int)((WE / 8) / 256);       // 4096

    setup_kernel<<<1, 256>>>(sel);
    convert_x<<<AA, 256>>>(x);
    // phase 1: per-expert gate+up
    for (int e = 0; e < EE; e++) {
        convert_gu<<<gu_blk, 256>>>(Wg, Wu, e);
        gemm_gateup<<<dim3(ETILES, FF / BN), 256>>>(e);
    }
    // phase 2: per-expert down (reuses g_wab)
    for (int e = 0; e < EE; e++) {
        convert_wd<<<wd_blk, 256>>>(Wd, e);
        gemm_down<<<dim3(ETILES, DD / DN), 256>>>(e);
    }
    combine_kernel<<<(TT * (DD / 4) + 255) / 256, 256>>>(rw, out);
}